// round 2
// baseline (speedup 1.0000x reference)
#include <cuda_runtime.h>
#include <cstdint>

#define N_NODES 100000
#define N_EDGES 1250000
#define D_IN 32
#define H 64

// scratch: post-MLP node features (gather source for message passing)
__device__ float g_h[(size_t)N_NODES * H];

// ---------------------------------------------------------------------------
// Kernel 1: fused node MLP  (x @ W1 + b1 -> LN -> ReLU -> @ W2 + b2 -> LN -> ReLU)
// One warp per node. Lane l owns output dims {l, l+32}.
// Writes result to g_h (gather source) AND d_out (out = h + aggr init).
// ---------------------------------------------------------------------------
__global__ __launch_bounds__(256) void mlp_kernel(
    const float* __restrict__ x,
    const float* __restrict__ W1, const float* __restrict__ b1,
    const float* __restrict__ g1, const float* __restrict__ be1,
    const float* __restrict__ W2, const float* __restrict__ b2,
    const float* __restrict__ g2, const float* __restrict__ be2,
    float* __restrict__ out)
{
    __shared__ float sW1[D_IN * H];      // 8 KB
    __shared__ float sW2[H * H];         // 16 KB
    __shared__ float sb1[H], sg1[H], sbe1[H];
    __shared__ float sb2[H], sg2[H], sbe2[H];
    __shared__ float sx[8][D_IN];        // per-warp x staging
    __shared__ float sh1[8][H];          // per-warp hidden staging

    const int tid = threadIdx.x;
    for (int i = tid; i < D_IN * H; i += 256) sW1[i] = W1[i];
    for (int i = tid; i < H * H;    i += 256) sW2[i] = W2[i];
    if (tid < H) {
        sb1[tid] = b1[tid]; sg1[tid] = g1[tid]; sbe1[tid] = be1[tid];
        sb2[tid] = b2[tid]; sg2[tid] = g2[tid]; sbe2[tid] = be2[tid];
    }
    __syncthreads();

    const int warp = tid >> 5;
    const int lane = tid & 31;
    const int gwarp = blockIdx.x * 8 + warp;
    const int stride = gridDim.x * 8;

    for (int n = gwarp; n < N_NODES; n += stride) {
        // load this node's x row (coalesced 128B)
        sx[warp][lane] = x[(size_t)n * D_IN + lane];
        __syncwarp();

        // ---- layer 1 ----
        float a0 = sb1[lane], a1 = sb1[lane + 32];
        #pragma unroll
        for (int k = 0; k < D_IN; k++) {
            float xv = sx[warp][k];                 // broadcast
            a0 += xv * sW1[k * H + lane];           // conflict-free
            a1 += xv * sW1[k * H + lane + 32];
        }
        // LN over 64 values held as 2/lane across the warp
        float s = a0 + a1, sq = a0 * a0 + a1 * a1;
        #pragma unroll
        for (int off = 16; off > 0; off >>= 1) {
            s  += __shfl_xor_sync(0xffffffffu, s,  off);
            sq += __shfl_xor_sync(0xffffffffu, sq, off);
        }
        float mu  = s * (1.0f / H);
        float var = sq * (1.0f / H) - mu * mu;
        float inv = rsqrtf(var + 1e-5f);
        a0 = (a0 - mu) * inv * sg1[lane]      + sbe1[lane];
        a1 = (a1 - mu) * inv * sg1[lane + 32] + sbe1[lane + 32];
        a0 = fmaxf(a0, 0.0f);
        a1 = fmaxf(a1, 0.0f);

        sh1[warp][lane]      = a0;
        sh1[warp][lane + 32] = a1;
        __syncwarp();

        // ---- layer 2 ----
        float c0 = sb2[lane], c1 = sb2[lane + 32];
        #pragma unroll
        for (int k = 0; k < H; k++) {
            float hv = sh1[warp][k];                // broadcast
            c0 += hv * sW2[k * H + lane];
            c1 += hv * sW2[k * H + lane + 32];
        }
        s = c0 + c1; sq = c0 * c0 + c1 * c1;
        #pragma unroll
        for (int off = 16; off > 0; off >>= 1) {
            s  += __shfl_xor_sync(0xffffffffu, s,  off);
            sq += __shfl_xor_sync(0xffffffffu, sq, off);
        }
        mu  = s * (1.0f / H);
        var = sq * (1.0f / H) - mu * mu;
        inv = rsqrtf(var + 1e-5f);
        c0 = (c0 - mu) * inv * sg2[lane]      + sbe2[lane];
        c1 = (c1 - mu) * inv * sg2[lane + 32] + sbe2[lane + 32];
        c0 = fmaxf(c0, 0.0f);
        c1 = fmaxf(c1, 0.0f);

        // write h (gather source) and out (= h, aggr added atomically later)
        size_t base = (size_t)n * H;
        g_h[base + lane]      = c0;
        g_h[base + lane + 32] = c1;
        out[base + lane]      = c0;
        out[base + lane + 32] = c1;
        __syncwarp();   // protect sx/sh1 reuse on next iteration
    }
}

// ---------------------------------------------------------------------------
// Kernel 2: edge scatter-add.  16 threads per edge, one float4 chunk each.
// out[row] += h[col] via red.global.add.v4.f32 (one 16B L2 reduction per thread)
// edge_index arrives as int32 (JAX downgrades int64 without x64 mode).
// ---------------------------------------------------------------------------
__global__ __launch_bounds__(256) void edge_kernel(
    const int* __restrict__ ei,   // [2, N_EDGES] int32: row = ei[0,:], col = ei[1,:]
    float* __restrict__ out)
{
    unsigned int t = blockIdx.x * 256u + threadIdx.x;
    unsigned int e = t >> 4;
    if (e >= N_EDGES) return;
    int c = (t & 15u) * 4;

    int row = ei[e];
    int col = ei[N_EDGES + e];
    // cheap safety: never fault on unexpected index content
    if ((unsigned)row >= N_NODES || (unsigned)col >= N_NODES) return;

    const float4 v = __ldg((const float4*)(g_h + (size_t)col * H + c));
    float* dst = out + (size_t)row * H + c;
    asm volatile("red.global.add.v4.f32 [%0], {%1,%2,%3,%4};"
                 :: "l"(dst), "f"(v.x), "f"(v.y), "f"(v.z), "f"(v.w)
                 : "memory");
}

// ---------------------------------------------------------------------------
// inputs (metadata order): x, edge_index, W1, b1, g1, beta1, W2, b2, g2, beta2
// ---------------------------------------------------------------------------
extern "C" void kernel_launch(void* const* d_in, const int* in_sizes, int n_in,
                              void* d_out, int out_size)
{
    const float* x   = (const float*)d_in[0];
    const int*   ei  = (const int*)d_in[1];
    const float* W1  = (const float*)d_in[2];
    const float* b1  = (const float*)d_in[3];
    const float* g1  = (const float*)d_in[4];
    const float* be1 = (const float*)d_in[5];
    const float* W2  = (const float*)d_in[6];
    const float* b2  = (const float*)d_in[7];
    const float* g2  = (const float*)d_in[8];
    const float* be2 = (const float*)d_in[9];
    float* out = (float*)d_out;

    // MLP: warp-per-node, 8 warps/block, grid-stride
    mlp_kernel<<<592, 256>>>(x, W1, b1, g1, be1, W2, b2, g2, be2, out);

    // scatter: 16 threads per edge
    unsigned int total = (unsigned int)N_EDGES * 16u;
    unsigned int blocks = (total + 255u) / 256u;
    edge_kernel<<<blocks, 256>>>(ei, out);
}

// round 3
// speedup vs baseline: 1.4412x; 1.4412x over previous
#include <cuda_runtime.h>
#include <cstdint>

#define N_NODES 100000
#define N_EDGES 1250000
#define D_IN 32
#define H 64
#define SCAN_B 1024
#define NB ((N_NODES + SCAN_B - 1) / SCAN_B)   // 98

// scratch
__device__ float g_h[(size_t)N_NODES * H];
__device__ int   g_deg[N_NODES];
__device__ int   g_off[N_NODES + 1];
__device__ int   g_pos[N_NODES];
__device__ int   g_csr_col[N_EDGES];
__device__ int   g_bsum[NB];
__device__ int   g_bbase[NB];

// ---------------------------------------------------------------------------
// Kernel 1: fused node MLP, 4 nodes per warp (weights reused across nodes).
// Lane l owns output dims {l, l+32} of each of its 4 nodes.
// ---------------------------------------------------------------------------
__global__ __launch_bounds__(256) void mlp_kernel(
    const float* __restrict__ x,
    const float* __restrict__ W1, const float* __restrict__ b1,
    const float* __restrict__ g1, const float* __restrict__ be1,
    const float* __restrict__ W2, const float* __restrict__ b2,
    const float* __restrict__ g2, const float* __restrict__ be2)
{
    __shared__ float sW1[D_IN * H];      // 8 KB
    __shared__ float sW2[H * H];         // 16 KB
    __shared__ float sb1[H], sg1[H], sbe1[H];
    __shared__ float sb2[H], sg2[H], sbe2[H];
    __shared__ __align__(16) float sx[8][4][D_IN];   // 4 KB
    __shared__ __align__(16) float sh[8][4][H];      // 8 KB

    const int tid = threadIdx.x;
    for (int i = tid; i < D_IN * H; i += 256) sW1[i] = W1[i];
    for (int i = tid; i < H * H;    i += 256) sW2[i] = W2[i];
    if (tid < H) {
        sb1[tid] = b1[tid]; sg1[tid] = g1[tid]; sbe1[tid] = be1[tid];
        sb2[tid] = b2[tid]; sg2[tid] = g2[tid]; sbe2[tid] = be2[tid];
    }
    __syncthreads();

    const int warp = tid >> 5;
    const int lane = tid & 31;
    const int n0 = (blockIdx.x * 8 + warp) * 4;
    if (n0 >= N_NODES) return;

    // stage 4 x rows (coalesced)
    #pragma unroll
    for (int j = 0; j < 4; j++)
        sx[warp][j][lane] = x[(size_t)(n0 + j) * D_IN + lane];
    __syncwarp();

    // ---- layer 1 ----
    float a[4][2];
    #pragma unroll
    for (int j = 0; j < 4; j++) { a[j][0] = sb1[lane]; a[j][1] = sb1[lane + 32]; }

    #pragma unroll
    for (int k4 = 0; k4 < D_IN / 4; k4++) {
        float4 xv[4];
        #pragma unroll
        for (int j = 0; j < 4; j++)
            xv[j] = *(const float4*)&sx[warp][j][k4 * 4];
        #pragma unroll
        for (int kk = 0; kk < 4; kk++) {
            const int k = k4 * 4 + kk;
            const float w0 = sW1[k * H + lane];
            const float w1 = sW1[k * H + lane + 32];
            #pragma unroll
            for (int j = 0; j < 4; j++) {
                const float xx = ((const float*)&xv[j])[kk];
                a[j][0] += xx * w0;
                a[j][1] += xx * w1;
            }
        }
    }

    // LN + ReLU for 4 nodes (warp reductions over 64 values = 2/lane)
    {
        float s[4], q[4];
        #pragma unroll
        for (int j = 0; j < 4; j++) {
            s[j] = a[j][0] + a[j][1];
            q[j] = a[j][0] * a[j][0] + a[j][1] * a[j][1];
        }
        #pragma unroll
        for (int off = 16; off > 0; off >>= 1) {
            #pragma unroll
            for (int j = 0; j < 4; j++) {
                s[j] += __shfl_xor_sync(0xffffffffu, s[j], off);
                q[j] += __shfl_xor_sync(0xffffffffu, q[j], off);
            }
        }
        #pragma unroll
        for (int j = 0; j < 4; j++) {
            const float mu  = s[j] * (1.0f / H);
            const float var = q[j] * (1.0f / H) - mu * mu;
            const float inv = rsqrtf(var + 1e-5f);
            float v0 = (a[j][0] - mu) * inv * sg1[lane]      + sbe1[lane];
            float v1 = (a[j][1] - mu) * inv * sg1[lane + 32] + sbe1[lane + 32];
            sh[warp][j][lane]      = fmaxf(v0, 0.0f);
            sh[warp][j][lane + 32] = fmaxf(v1, 0.0f);
        }
    }
    __syncwarp();

    // ---- layer 2 ----
    float c[4][2];
    #pragma unroll
    for (int j = 0; j < 4; j++) { c[j][0] = sb2[lane]; c[j][1] = sb2[lane + 32]; }

    #pragma unroll
    for (int k4 = 0; k4 < H / 4; k4++) {
        float4 hv[4];
        #pragma unroll
        for (int j = 0; j < 4; j++)
            hv[j] = *(const float4*)&sh[warp][j][k4 * 4];
        #pragma unroll
        for (int kk = 0; kk < 4; kk++) {
            const int k = k4 * 4 + kk;
            const float w0 = sW2[k * H + lane];
            const float w1 = sW2[k * H + lane + 32];
            #pragma unroll
            for (int j = 0; j < 4; j++) {
                const float hh = ((const float*)&hv[j])[kk];
                c[j][0] += hh * w0;
                c[j][1] += hh * w1;
            }
        }
    }

    {
        float s[4], q[4];
        #pragma unroll
        for (int j = 0; j < 4; j++) {
            s[j] = c[j][0] + c[j][1];
            q[j] = c[j][0] * c[j][0] + c[j][1] * c[j][1];
        }
        #pragma unroll
        for (int off = 16; off > 0; off >>= 1) {
            #pragma unroll
            for (int j = 0; j < 4; j++) {
                s[j] += __shfl_xor_sync(0xffffffffu, s[j], off);
                q[j] += __shfl_xor_sync(0xffffffffu, q[j], off);
            }
        }
        #pragma unroll
        for (int j = 0; j < 4; j++) {
            const float mu  = s[j] * (1.0f / H);
            const float var = q[j] * (1.0f / H) - mu * mu;
            const float inv = rsqrtf(var + 1e-5f);
            float v0 = (c[j][0] - mu) * inv * sg2[lane]      + sbe2[lane];
            float v1 = (c[j][1] - mu) * inv * sg2[lane + 32] + sbe2[lane + 32];
            const size_t base = (size_t)(n0 + j) * H;
            g_h[base + lane]      = fmaxf(v0, 0.0f);
            g_h[base + lane + 32] = fmaxf(v1, 0.0f);
        }
    }
}

// ---------------------------------------------------------------------------
// CSR build: zero -> histogram -> 2-level scan -> scatter
// ---------------------------------------------------------------------------
__global__ void zero_deg_kernel() {
    int i = blockIdx.x * blockDim.x + threadIdx.x;
    if (i < N_NODES) g_deg[i] = 0;
}

__global__ void hist_kernel(const int* __restrict__ ei) {
    int e = blockIdx.x * blockDim.x + threadIdx.x;
    if (e >= N_EDGES) return;
    int row = ei[e];
    if ((unsigned)row < N_NODES) atomicAdd(&g_deg[row], 1);
}

__global__ __launch_bounds__(SCAN_B) void scan1_kernel() {
    __shared__ int wsum[32];
    const int t = threadIdx.x;
    const int i = blockIdx.x * SCAN_B + t;
    int v = (i < N_NODES) ? g_deg[i] : 0;
    const int orig = v;
    #pragma unroll
    for (int o = 1; o < 32; o <<= 1) {
        int n = __shfl_up_sync(0xffffffffu, v, o);
        if ((t & 31) >= o) v += n;
    }
    if ((t & 31) == 31) wsum[t >> 5] = v;
    __syncthreads();
    if (t < 32) {
        int w = wsum[t];
        #pragma unroll
        for (int o = 1; o < 32; o <<= 1) {
            int n = __shfl_up_sync(0xffffffffu, w, o);
            if (t >= o) w += n;
        }
        wsum[t] = w;
    }
    __syncthreads();
    const int base = (t >= 32) ? wsum[(t >> 5) - 1] : 0;
    const int incl = v + base;
    if (i < N_NODES) g_off[i] = incl - orig;      // block-local exclusive
    if (t == SCAN_B - 1) g_bsum[blockIdx.x] = incl;
}

__global__ __launch_bounds__(128) void scan2_kernel() {
    __shared__ int ws[4];
    const int t = threadIdx.x;
    int v = (t < NB) ? g_bsum[t] : 0;
    const int orig = v;
    #pragma unroll
    for (int o = 1; o < 32; o <<= 1) {
        int n = __shfl_up_sync(0xffffffffu, v, o);
        if ((t & 31) >= o) v += n;
    }
    if ((t & 31) == 31) ws[t >> 5] = v;
    __syncthreads();
    if (t < 4) {
        int w = ws[t];
        #pragma unroll
        for (int o = 1; o < 4; o <<= 1) {
            int n = __shfl_up_sync(0x0000000fu, w, o, 4);
            if (t >= o) w += n;
        }
        ws[t] = w;
    }
    __syncthreads();
    const int base = (t >= 32) ? ws[(t >> 5) - 1] : 0;
    if (t < NB) g_bbase[t] = v + base - orig;     // exclusive block base
}

__global__ __launch_bounds__(SCAN_B) void scan3_kernel() {
    const int i = blockIdx.x * SCAN_B + threadIdx.x;
    if (i < N_NODES) {
        const int o = g_off[i] + g_bbase[blockIdx.x];
        g_off[i] = o;
        g_pos[i] = o;
    }
    if (i == 0) g_off[N_NODES] = N_EDGES;
}

__global__ void scatter_kernel(const int* __restrict__ ei) {
    int e = blockIdx.x * blockDim.x + threadIdx.x;
    if (e >= N_EDGES) return;
    int row = ei[e];
    int col = ei[N_EDGES + e];
    if ((unsigned)row >= N_NODES) return;
    int p = atomicAdd(&g_pos[row], 1);
    g_csr_col[p] = col;
}

// ---------------------------------------------------------------------------
// Gather: warp per node. acc = h[n] + sum over in-neighbors h[col].
// float2 per lane -> one coalesced 256B load per edge per warp.
// ---------------------------------------------------------------------------
__global__ __launch_bounds__(256) void gather_kernel(float* __restrict__ out)
{
    const int n = blockIdx.x * 8 + (threadIdx.x >> 5);
    if (n >= N_NODES) return;
    const int lane = threadIdx.x & 31;

    const float2* __restrict__ h2 = (const float2*)g_h;
    float2 acc = h2[(size_t)n * 32 + lane];       // self term (out = h + aggr)

    const int start = g_off[n];
    const int end   = g_off[n + 1];

    for (int j = start; j < end; j += 32) {
        const int cnt = min(32, end - j);
        int cidx = (lane < cnt) ? g_csr_col[j + lane] : 0;
        for (int t = 0; t < cnt; t++) {
            const int cc = __shfl_sync(0xffffffffu, cidx, t);
            const float2 v = __ldg(&h2[(size_t)cc * 32 + lane]);
            acc.x += v.x;
            acc.y += v.y;
        }
    }
    ((float2*)out)[(size_t)n * 32 + lane] = acc;
}

// ---------------------------------------------------------------------------
// inputs: x, edge_index(int32 [2,E]), W1, b1, g1, beta1, W2, b2, g2, beta2
// ---------------------------------------------------------------------------
extern "C" void kernel_launch(void* const* d_in, const int* in_sizes, int n_in,
                              void* d_out, int out_size)
{
    const float* x   = (const float*)d_in[0];
    const int*   ei  = (const int*)d_in[1];
    const float* W1  = (const float*)d_in[2];
    const float* b1  = (const float*)d_in[3];
    const float* g1  = (const float*)d_in[4];
    const float* be1 = (const float*)d_in[5];
    const float* W2  = (const float*)d_in[6];
    const float* b2  = (const float*)d_in[7];
    const float* g2  = (const float*)d_in[8];
    const float* be2 = (const float*)d_in[9];
    float* out = (float*)d_out;

    // node MLP: 4 nodes/warp, 32 nodes/block, exact grid
    mlp_kernel<<<(N_NODES + 31) / 32, 256>>>(x, W1, b1, g1, be1, W2, b2, g2, be2);

    // CSR build
    zero_deg_kernel<<<(N_NODES + 255) / 256, 256>>>();
    hist_kernel<<<(N_EDGES + 255) / 256, 256>>>(ei);
    scan1_kernel<<<NB, SCAN_B>>>();
    scan2_kernel<<<1, 128>>>();
    scan3_kernel<<<NB, SCAN_B>>>();
    scatter_kernel<<<(N_EDGES + 255) / 256, 256>>>(ei);

    // pull-gather (no atomics on feature data)
    gather_kernel<<<(N_NODES + 7) / 8, 256>>>(out);
}

// round 4
// speedup vs baseline: 1.4752x; 1.0236x over previous
#include <cuda_runtime.h>
#include <cstdint>

#define N_NODES 100000
#define N_EDGES 1250000
#define D_IN 32
#define H 64
#define SCAN_B 1024
#define NB ((N_NODES + SCAN_B - 1) / SCAN_B)   // 98
#define MLPB ((N_NODES + 31) / 32)             // 3125 blocks, 4 nodes/warp
#define HISTB 1024                              // hist blocks appended to MLP grid

// scratch
__device__ float g_h[(size_t)N_NODES * H];
__device__ int   g_deg[N_NODES];
__device__ int   g_off[N_NODES + 1];
__device__ int   g_pos[N_NODES];
__device__ int   g_csr_col[N_EDGES];
__device__ int   g_flag[NB];                    // decoupled-lookback: agg+1 (0 = not ready)

// ---- packed f32x2 helpers (sm_103a dual-FMA) --------------------------------
__device__ __forceinline__ unsigned long long pk2(float lo, float hi) {
    unsigned long long r;
    asm("mov.b64 %0, {%1, %2};" : "=l"(r) : "f"(lo), "f"(hi));
    return r;
}
__device__ __forceinline__ void upk2(unsigned long long v, float& lo, float& hi) {
    asm("mov.b64 {%0, %1}, %2;" : "=f"(lo), "=f"(hi) : "l"(v));
}
__device__ __forceinline__ void fma2(unsigned long long& d, unsigned long long a,
                                     unsigned long long b) {
    asm("fma.rn.f32x2 %0, %1, %2, %0;" : "+l"(d) : "l"(a), "l"(b));
}

// ---------------------------------------------------------------------------
// K1 (fat): blocks [0, MLPB) = fused node MLP (4 nodes/warp, FFMA2 mainloop)
//           blocks [MLPB, MLPB+HISTB) = degree histogram (overlaps MLP)
// ---------------------------------------------------------------------------
__global__ __launch_bounds__(256) void mlp_hist_kernel(
    const float* __restrict__ x, const int* __restrict__ ei,
    const float* __restrict__ W1, const float* __restrict__ b1,
    const float* __restrict__ g1, const float* __restrict__ be1,
    const float* __restrict__ W2, const float* __restrict__ b2,
    const float* __restrict__ g2, const float* __restrict__ be2)
{
    const int tid = threadIdx.x;

    if (blockIdx.x >= MLPB) {
        // ---- histogram part ----
        const int base = (blockIdx.x - MLPB) * 256 + tid;
        for (int e = base; e < N_EDGES; e += HISTB * 256) {
            int row = ei[e];
            if ((unsigned)row < N_NODES) atomicAdd(&g_deg[row], 1);
        }
        return;
    }

    // ---- MLP part ----
    __shared__ __align__(16) float sW1p[D_IN * H];   // paired: [k*32+c] = (W[k][c], W[k][c+32])
    __shared__ __align__(16) float sW2p[H * H];
    __shared__ float sb1[H], sg1[H], sbe1[H];
    __shared__ float sb2[H], sg2[H], sbe2[H];
    __shared__ __align__(16) float sx[8][4][D_IN];
    __shared__ __align__(16) float sh[8][4][H];

    for (int i = tid; i < D_IN * H; i += 256) {
        int k = i >> 6, d = i & 63;
        sW1p[(k * 32 + (d & 31)) * 2 + (d >> 5)] = W1[i];
    }
    for (int i = tid; i < H * H; i += 256) {
        int k = i >> 6, d = i & 63;
        sW2p[(k * 32 + (d & 31)) * 2 + (d >> 5)] = W2[i];
    }
    if (tid < H) {
        sb1[tid] = b1[tid]; sg1[tid] = g1[tid]; sbe1[tid] = be1[tid];
        sb2[tid] = b2[tid]; sg2[tid] = g2[tid]; sbe2[tid] = be2[tid];
    }
    __syncthreads();

    const int warp = tid >> 5;
    const int lane = tid & 31;
    const int n0 = (blockIdx.x * 8 + warp) * 4;
    if (n0 >= N_NODES) return;

    const unsigned long long* W1p64 = (const unsigned long long*)sW1p;
    const unsigned long long* W2p64 = (const unsigned long long*)sW2p;

    #pragma unroll
    for (int j = 0; j < 4; j++)
        sx[warp][j][lane] = x[(size_t)(n0 + j) * D_IN + lane];
    __syncwarp();

    // ---- layer 1 ----
    unsigned long long a[4];
    {
        const unsigned long long bias = pk2(sb1[lane], sb1[lane + 32]);
        #pragma unroll
        for (int j = 0; j < 4; j++) a[j] = bias;
    }
    #pragma unroll
    for (int k4 = 0; k4 < D_IN / 4; k4++) {
        float4 xv[4];
        #pragma unroll
        for (int j = 0; j < 4; j++) xv[j] = *(const float4*)&sx[warp][j][k4 * 4];
        #pragma unroll
        for (int kk = 0; kk < 4; kk++) {
            const int k = k4 * 4 + kk;
            const unsigned long long w = W1p64[k * 32 + lane];
            #pragma unroll
            for (int j = 0; j < 4; j++) {
                const float xx = ((const float*)&xv[j])[kk];
                fma2(a[j], pk2(xx, xx), w);
            }
        }
    }
    {
        float s[4], q[4], v0[4], v1[4];
        #pragma unroll
        for (int j = 0; j < 4; j++) {
            upk2(a[j], v0[j], v1[j]);
            s[j] = v0[j] + v1[j];
            q[j] = v0[j] * v0[j] + v1[j] * v1[j];
        }
        #pragma unroll
        for (int off = 16; off > 0; off >>= 1) {
            #pragma unroll
            for (int j = 0; j < 4; j++) {
                s[j] += __shfl_xor_sync(0xffffffffu, s[j], off);
                q[j] += __shfl_xor_sync(0xffffffffu, q[j], off);
            }
        }
        #pragma unroll
        for (int j = 0; j < 4; j++) {
            const float mu  = s[j] * (1.0f / H);
            const float var = q[j] * (1.0f / H) - mu * mu;
            const float inv = rsqrtf(var + 1e-5f);
            float r0 = (v0[j] - mu) * inv * sg1[lane]      + sbe1[lane];
            float r1 = (v1[j] - mu) * inv * sg1[lane + 32] + sbe1[lane + 32];
            sh[warp][j][lane]      = fmaxf(r0, 0.0f);
            sh[warp][j][lane + 32] = fmaxf(r1, 0.0f);
        }
    }
    __syncwarp();

    // ---- layer 2 ----
    unsigned long long c[4];
    {
        const unsigned long long bias = pk2(sb2[lane], sb2[lane + 32]);
        #pragma unroll
        for (int j = 0; j < 4; j++) c[j] = bias;
    }
    #pragma unroll
    for (int k4 = 0; k4 < H / 4; k4++) {
        float4 hv[4];
        #pragma unroll
        for (int j = 0; j < 4; j++) hv[j] = *(const float4*)&sh[warp][j][k4 * 4];
        #pragma unroll
        for (int kk = 0; kk < 4; kk++) {
            const int k = k4 * 4 + kk;
            const unsigned long long w = W2p64[k * 32 + lane];
            #pragma unroll
            for (int j = 0; j < 4; j++) {
                const float hh = ((const float*)&hv[j])[kk];
                fma2(c[j], pk2(hh, hh), w);
            }
        }
    }
    {
        float s[4], q[4], v0[4], v1[4];
        #pragma unroll
        for (int j = 0; j < 4; j++) {
            upk2(c[j], v0[j], v1[j]);
            s[j] = v0[j] + v1[j];
            q[j] = v0[j] * v0[j] + v1[j] * v1[j];
        }
        #pragma unroll
        for (int off = 16; off > 0; off >>= 1) {
            #pragma unroll
            for (int j = 0; j < 4; j++) {
                s[j] += __shfl_xor_sync(0xffffffffu, s[j], off);
                q[j] += __shfl_xor_sync(0xffffffffu, q[j], off);
            }
        }
        #pragma unroll
        for (int j = 0; j < 4; j++) {
            const float mu  = s[j] * (1.0f / H);
            const float var = q[j] * (1.0f / H) - mu * mu;
            const float inv = rsqrtf(var + 1e-5f);
            float r0 = (v0[j] - mu) * inv * sg2[lane]      + sbe2[lane];
            float r1 = (v1[j] - mu) * inv * sg2[lane + 32] + sbe2[lane + 32];
            const size_t base = (size_t)(n0 + j) * H;
            g_h[base + lane]      = fmaxf(r0, 0.0f);
            g_h[base + lane + 32] = fmaxf(r1, 0.0f);
        }
    }
}

// ---------------------------------------------------------------------------
// K2: single-kernel exclusive scan of g_deg -> g_off/g_pos (decoupled lookback)
// All NB=98 blocks resident in wave 1 (148 SMs) -> lookback cannot deadlock.
// ---------------------------------------------------------------------------
__global__ __launch_bounds__(SCAN_B) void scan_kernel()
{
    __shared__ int wsum[32];
    __shared__ int sprefix;
    const int t   = threadIdx.x;
    const int bid = blockIdx.x;
    const int i   = bid * SCAN_B + t;

    int v = (i < N_NODES) ? g_deg[i] : 0;
    const int orig = v;
    #pragma unroll
    for (int o = 1; o < 32; o <<= 1) {
        int n = __shfl_up_sync(0xffffffffu, v, o);
        if ((t & 31) >= o) v += n;
    }
    if ((t & 31) == 31) wsum[t >> 5] = v;
    __syncthreads();
    if (t < 32) {
        int w = wsum[t];
        #pragma unroll
        for (int o = 1; o < 32; o <<= 1) {
            int n = __shfl_up_sync(0xffffffffu, w, o);
            if (t >= o) w += n;
        }
        wsum[t] = w;
    }
    __syncthreads();
    const int base = (t >= 32) ? wsum[(t >> 5) - 1] : 0;
    const int incl = v + base;                      // block-local inclusive

    // publish block aggregate (value+1 in one word; 0 = not ready)
    if (t == SCAN_B - 1) {
        ((volatile int*)g_flag)[bid] = incl + 1;
    }

    // lookback: warp 0 sums all predecessor aggregates
    if (t < 32) {
        int sum = 0;
        for (int j0 = bid - 1; j0 >= 0; j0 -= 32) {
            const int j = j0 - t;
            int av = 0;
            if (j >= 0) {
                while ((av = ((volatile int*)g_flag)[j]) == 0) {}
                av -= 1;
            }
            #pragma unroll
            for (int o = 16; o > 0; o >>= 1)
                av += __shfl_xor_sync(0xffffffffu, av, o);
            sum += av;
        }
        if (t == 0) sprefix = sum;
    }
    __syncthreads();

    if (i < N_NODES) {
        const int o = sprefix + incl - orig;        // global exclusive
        g_off[i] = o;
        g_pos[i] = o;
    }
    if (i == 0) g_off[N_NODES] = N_EDGES;
}

// ---------------------------------------------------------------------------
// K3: scatter column ids into CSR slots
// ---------------------------------------------------------------------------
__global__ __launch_bounds__(256) void scatter_kernel(const int* __restrict__ ei)
{
    int e = blockIdx.x * 256 + threadIdx.x;
    if (e >= N_EDGES) return;
    int row = ei[e];
    int col = ei[N_EDGES + e];
    if ((unsigned)row >= N_NODES) return;
    int p = atomicAdd(&g_pos[row], 1);
    g_csr_col[p] = col;
}

// ---------------------------------------------------------------------------
// K4: pull-gather, warp per node, 2 edges in flight per warp.
// Half-warp h (lanes 16h..16h+15) accumulates a full 64-float row (float4/lane)
// over edges t = 2i+h; halves combined by shuffle at the end.
// ---------------------------------------------------------------------------
__global__ __launch_bounds__(256) void gather_kernel(float* __restrict__ out)
{
    const int n = blockIdx.x * 8 + (threadIdx.x >> 5);
    if (n >= N_NODES) return;
    const int lane = threadIdx.x & 31;
    const int half = lane >> 4;
    const int hl   = lane & 15;

    float4 acc = make_float4(0.f, 0.f, 0.f, 0.f);

    const int start = g_off[n];
    const int end   = g_off[n + 1];

    for (int jb = start; jb < end; jb += 32) {
        const int cnt = min(32, end - jb);
        int cidx = (lane < cnt) ? g_csr_col[jb + lane] : 0;
        const int iters = (cnt + 1) >> 1;
        for (int it = 0; it < iters; it++) {
            const int tt = 2 * it + half;
            const int cc = __shfl_sync(0xffffffffu, cidx, tt & 31);
            if (tt < cnt) {
                const float4 v = __ldg((const float4*)(g_h + (size_t)cc * H) + hl);
                acc.x += v.x; acc.y += v.y; acc.z += v.z; acc.w += v.w;
            }
        }
    }

    // combine halves: lanes 0-15 += lanes 16-31
    acc.x += __shfl_down_sync(0xffffffffu, acc.x, 16);
    acc.y += __shfl_down_sync(0xffffffffu, acc.y, 16);
    acc.z += __shfl_down_sync(0xffffffffu, acc.z, 16);
    acc.w += __shfl_down_sync(0xffffffffu, acc.w, 16);

    if (lane < 16) {
        const float4 self = __ldg((const float4*)(g_h + (size_t)n * H) + hl);
        acc.x += self.x; acc.y += self.y; acc.z += self.z; acc.w += self.w;
        ((float4*)out)[(size_t)n * 16 + hl] = acc;
    }
}

// ---------------------------------------------------------------------------
// inputs: x, edge_index(int32 [2,E]), W1, b1, g1, beta1, W2, b2, g2, beta2
// ---------------------------------------------------------------------------
extern "C" void kernel_launch(void* const* d_in, const int* in_sizes, int n_in,
                              void* d_out, int out_size)
{
    const float* x   = (const float*)d_in[0];
    const int*   ei  = (const int*)d_in[1];
    const float* W1  = (const float*)d_in[2];
    const float* b1  = (const float*)d_in[3];
    const float* g1  = (const float*)d_in[4];
    const float* be1 = (const float*)d_in[5];
    const float* W2  = (const float*)d_in[6];
    const float* b2  = (const float*)d_in[7];
    const float* g2  = (const float*)d_in[8];
    const float* be2 = (const float*)d_in[9];
    float* out = (float*)d_out;

    void* p_deg  = nullptr;
    void* p_flag = nullptr;
    cudaGetSymbolAddress(&p_deg,  g_deg);
    cudaGetSymbolAddress(&p_flag, g_flag);
    cudaMemsetAsync(p_deg,  0, sizeof(int) * N_NODES);
    cudaMemsetAsync(p_flag, 0, sizeof(int) * NB);

    mlp_hist_kernel<<<MLPB + HISTB, 256>>>(x, ei, W1, b1, g1, be1, W2, b2, g2, be2);
    scan_kernel<<<NB, SCAN_B>>>();
    scatter_kernel<<<(N_EDGES + 255) / 256, 256>>>(ei);
    gather_kernel<<<(N_NODES + 7) / 8, 256>>>(out);
}